// round 3
// baseline (speedup 1.0000x reference)
#include <cuda_runtime.h>
#include <math.h>
#include <float.h>
#include <stdint.h>

#define NN 8192
#define DD 128
#define TOPK 30

// ---- scratch (device globals; no runtime allocation allowed) ----
__device__ float g_M1t[DD * NN];              // M1^T  [128][8192]
__device__ float g_M2t[DD * NN];              // M2^T  [128][8192]
__device__ float g_A[(size_t)NN * NN];        // A scratch, 256 MB

// ============================================================================
// XLA/Eigen f32 tanh replica (EmitTanh / generic_fast_tanh_float).
// ============================================================================
__device__ __forceinline__ float xla_tanh(float x) {
    const float kClamp = 7.90531110763549805f;
    const bool tiny = fabsf(x) < 0.0004f;
    float xc = fminf(fmaxf(x, -kClamp), kClamp);
    float x2 = xc * xc;
    float p = fmaf(x2, -2.76076847742355e-16f, 2.00018790482477e-13f);
    p = fmaf(x2, p, -8.60467152213735e-11f);
    p = fmaf(x2, p, 5.12229709037114e-08f);
    p = fmaf(x2, p, 1.48572235717979e-05f);
    p = fmaf(x2, p, 6.37261928875436e-04f);
    p = fmaf(x2, p, 4.89352455891786e-03f);
    p = xc * p;
    float q = fmaf(x2, 1.19825839466702e-06f, 1.18534705686654e-04f);
    q = fmaf(x2, q, 2.26843463243900e-03f);
    q = fmaf(x2, q, 4.89352518554385e-03f);
    float r = __fdiv_rn(p, q);   // IEEE divide regardless of fast-math flags
    return tiny ? x : r;
}

// ============================================================================
// Kernel 1: M = tanh(3*(E @ W^T + b)); write transposed into g_M1t/g_M2t,
// selected by `mode` IN DEVICE CODE (passing __device__ symbols from host is
// invalid — that was the round-2 bug).
// Bit-exact chain: ascending-k serial FMA, FADD bias, FMUL 3.0, XLA tanh.
// grid: 256 blocks x 256 thr, 32 rows per block. dyn smem = 81920 B.
// ============================================================================
__global__ void prep_kernel(const float* __restrict__ E,
                            const float* __restrict__ W,
                            const float* __restrict__ b,
                            int mode)
{
    extern __shared__ float sh[];
    float* Ws = sh;               // 128*128
    float* Es = sh + DD * DD;     // 32*128
    __shared__ float bs[DD];

    float* __restrict__ Mt = (mode == 0) ? g_M1t : g_M2t;

    const int tid = threadIdx.x;
    const int row0 = blockIdx.x * 32;

    {
        const float4* W4 = (const float4*)W;
        float4* Ws4 = (float4*)Ws;
        #pragma unroll 4
        for (int i = tid; i < DD * DD / 4; i += 256) Ws4[i] = W4[i];
        const float4* E4 = (const float4*)(E + (size_t)row0 * DD);
        float4* Es4 = (float4*)Es;
        #pragma unroll
        for (int i = tid; i < 32 * DD / 4; i += 256) Es4[i] = E4[i];
        if (tid < DD) bs[tid] = b[tid];
    }
    __syncthreads();

    const int tx = tid & 7;    // row group (4 rows)
    const int ty = tid >> 3;   // d group (4 cols)

    float acc[4][4];
    #pragma unroll
    for (int r = 0; r < 4; r++)
        #pragma unroll
        for (int c = 0; c < 4; c++) acc[r][c] = 0.0f;

    #pragma unroll 8
    for (int k = 0; k < DD; k += 4) {
        float4 ev[4], wv[4];
        #pragma unroll
        for (int r = 0; r < 4; r++) ev[r] = *(const float4*)&Es[(tx * 4 + r) * DD + k];
        #pragma unroll
        for (int c = 0; c < 4; c++) wv[c] = *(const float4*)&Ws[(ty * 4 + c) * DD + k];
        #pragma unroll
        for (int r = 0; r < 4; r++)
            #pragma unroll
            for (int c = 0; c < 4; c++) {
                // ascending-k serial FMA chain (matches Eigen/cuBLAS order)
                acc[r][c] = fmaf(ev[r].x, wv[c].x, acc[r][c]);
                acc[r][c] = fmaf(ev[r].y, wv[c].y, acc[r][c]);
                acc[r][c] = fmaf(ev[r].z, wv[c].z, acc[r][c]);
                acc[r][c] = fmaf(ev[r].w, wv[c].w, acc[r][c]);
            }
    }

    #pragma unroll
    for (int r = 0; r < 4; r++) {
        const int row = row0 + tx * 4 + r;
        #pragma unroll
        for (int c = 0; c < 4; c++) {
            const int d = ty * 4 + c;
            const float t = acc[r][c] + bs[d];   // FADD
            const float u = 3.0f * t;            // FMUL
            Mt[(size_t)d * NN + row] = xla_tanh(u);
        }
    }
}

// ============================================================================
// Kernel 2: P = M1@M2^T, Q = M2@M1^T as separate ascending-k FMA chains.
// A[i,j] = relu(P-Q); antisymmetry (bitwise: P_ji==Q_ij, Q_ji==P_ij) lets us
// compute only tiles bj>=bi and write A[j,i] = relu(Q-P).
// 128x128 tile, BK=16, cp.async double-buffered, 256 thr, 8x8x2 accs.
// dyn smem = 65536 B.
// ============================================================================
#define BK 16
#define NCHUNK (DD / BK)

__device__ __forceinline__ void cp16(uint32_t smem_dst, const float* gsrc) {
    asm volatile("cp.async.ca.shared.global [%0], [%1], 16;\n"
                 :: "r"(smem_dst), "l"(gsrc));
}

__global__ void __launch_bounds__(256) gemm_kernel()
{
    const int bi = blockIdx.y;
    const int bj = blockIdx.x;
    if (bj < bi) return;

    extern __shared__ float sh[];
    // per buffer: [M1I | M1J | M2I | M2J], each BK*128 floats
    const int ARR = BK * 128;
    const int BUF = 4 * ARR;

    const int I0 = bi * 128, J0 = bj * 128;
    const int tid = threadIdx.x;
    const int tx = tid & 15;   // 16 col groups of 8
    const int ty = tid >> 4;   // 16 row groups of 8

    const uint32_t sbase = (uint32_t)__cvta_generic_to_shared(sh);

    // 8 float4 loads per thread per chunk: f = tid + 256*j
    // la = f>>9 (0:M1I 1:M1J 2:M2I 3:M2J), k = (f&511)>>5, quad = f&31
    int la[8], lk[8], lq[8];
    #pragma unroll
    for (int j = 0; j < 8; j++) {
        const int f = tid + 256 * j;
        la[j] = f >> 9;
        lk[j] = (f & 511) >> 5;
        lq[j] = f & 31;
    }

    auto issue_chunk = [&](int c, int buf) {
        const int kb = c * BK;
        #pragma unroll
        for (int j = 0; j < 8; j++) {
            const size_t gk = (size_t)(kb + lk[j]) * NN;
            const int col = ((la[j] & 1) ? J0 : I0) + lq[j] * 4;
            const float* src = ((la[j] & 2) ? g_M2t : g_M1t) + gk + col;
            cp16(sbase + (uint32_t)((buf * BUF + la[j] * ARR + lk[j] * 128 + lq[j] * 4) * 4), src);
        }
        asm volatile("cp.async.commit_group;\n");
    };

    issue_chunk(0, 0);

    float accP[8][8], accQ[8][8];
    #pragma unroll
    for (int r = 0; r < 8; r++)
        #pragma unroll
        for (int s = 0; s < 8; s++) { accP[r][s] = 0.0f; accQ[r][s] = 0.0f; }

    for (int c = 0; c < NCHUNK; c++) {
        const int cur = c & 1;
        if (c < NCHUNK - 1) {
            issue_chunk(c + 1, cur ^ 1);
            asm volatile("cp.async.wait_group 1;\n");
        } else {
            asm volatile("cp.async.wait_group 0;\n");
        }
        __syncthreads();

        const float* M1I = sh + cur * BUF + 0 * ARR;
        const float* M1J = sh + cur * BUF + 1 * ARR;
        const float* M2I = sh + cur * BUF + 2 * ARR;
        const float* M2J = sh + cur * BUF + 3 * ARR;

        #pragma unroll
        for (int kk = 0; kk < BK; kk++) {
            float a1[8], a2[8], b1[8], b2[8];
            {
                float4 t0 = *(const float4*)&M1I[kk * 128 + ty * 8];
                float4 t1 = *(const float4*)&M1I[kk * 128 + ty * 8 + 4];
                a1[0]=t0.x; a1[1]=t0.y; a1[2]=t0.z; a1[3]=t0.w;
                a1[4]=t1.x; a1[5]=t1.y; a1[6]=t1.z; a1[7]=t1.w;
                float4 u0 = *(const float4*)&M2I[kk * 128 + ty * 8];
                float4 u1 = *(const float4*)&M2I[kk * 128 + ty * 8 + 4];
                a2[0]=u0.x; a2[1]=u0.y; a2[2]=u0.z; a2[3]=u0.w;
                a2[4]=u1.x; a2[5]=u1.y; a2[6]=u1.z; a2[7]=u1.w;
                float4 v0 = *(const float4*)&M1J[kk * 128 + tx * 8];
                float4 v1 = *(const float4*)&M1J[kk * 128 + tx * 8 + 4];
                b1[0]=v0.x; b1[1]=v0.y; b1[2]=v0.z; b1[3]=v0.w;
                b1[4]=v1.x; b1[5]=v1.y; b1[6]=v1.z; b1[7]=v1.w;
                float4 w0 = *(const float4*)&M2J[kk * 128 + tx * 8];
                float4 w1 = *(const float4*)&M2J[kk * 128 + tx * 8 + 4];
                b2[0]=w0.x; b2[1]=w0.y; b2[2]=w0.z; b2[3]=w0.w;
                b2[4]=w1.x; b2[5]=w1.y; b2[6]=w1.z; b2[7]=w1.w;
            }
            #pragma unroll
            for (int r = 0; r < 8; r++)
                #pragma unroll
                for (int s = 0; s < 8; s++) {
                    accP[r][s] = fmaf(a1[r], b2[s], accP[r][s]);  // M1_i . M2_j
                    accQ[r][s] = fmaf(a2[r], b1[s], accQ[r][s]);  // M2_i . M1_j
                }
        }
        __syncthreads();
    }

    const int ibase = I0 + ty * 8;
    const int jbase = J0 + tx * 8;

    if (bi == bj) {
        #pragma unroll
        for (int r = 0; r < 8; r++) {
            const int ig = ibase + r;
            #pragma unroll
            for (int sg = 0; sg < 2; sg++) {
                float4 w;
                float* wp = &w.x;
                #pragma unroll
                for (int cc = 0; cc < 4; cc++) {
                    const int jg = jbase + sg * 4 + cc;
                    float x = fmaxf(accP[r][sg * 4 + cc] - accQ[r][sg * 4 + cc], 0.0f);
                    if (ig == jg) x = 0.0f;
                    wp[cc] = x;
                }
                *(float4*)&g_A[(size_t)ig * NN + jbase + sg * 4] = w;
            }
        }
    } else {
        // direct tile (I,J): relu(P - Q)
        #pragma unroll
        for (int r = 0; r < 8; r++) {
            #pragma unroll
            for (int sg = 0; sg < 2; sg++) {
                float4 w;
                float* wp = &w.x;
                #pragma unroll
                for (int cc = 0; cc < 4; cc++)
                    wp[cc] = fmaxf(accP[r][sg * 4 + cc] - accQ[r][sg * 4 + cc], 0.0f);
                *(float4*)&g_A[(size_t)(ibase + r) * NN + jbase + sg * 4] = w;
            }
        }
        // transposed tile (J,I): relu(Q - P)  (bitwise == reference's P_ji - Q_ji)
        #pragma unroll
        for (int s = 0; s < 8; s++) {
            const int jg = jbase + s;
            #pragma unroll
            for (int rg = 0; rg < 2; rg++) {
                float4 w;
                float* wp = &w.x;
                #pragma unroll
                for (int cc = 0; cc < 4; cc++)
                    wp[cc] = fmaxf(accQ[rg * 4 + cc][s] - accP[rg * 4 + cc][s], 0.0f);
                *(float4*)&g_A[(size_t)jg * NN + ibase + rg * 4] = w;
            }
        }
    }
}

// ============================================================================
// Kernel 3: per-row top-30, stable descending (lower index wins ties),
// zero output A row, scatter vals, emit edge list.
// ============================================================================
__global__ void __launch_bounds__(256) topk_kernel(float* __restrict__ out,
                                                   long long abase,
                                                   int write_edges)
{
    const int row = blockIdx.x;
    const int tid = threadIdx.x;
    const float* arow = g_A + (size_t)row * NN;
    float* orow = out + abase + (size_t)row * NN;

    float v[32];
    const float4 z4 = make_float4(0.f, 0.f, 0.f, 0.f);
    #pragma unroll
    for (int q = 0; q < 8; q++) {
        const int base = (tid + 256 * q) * 4;
        float4 t = *(const float4*)&arow[base];
        v[q * 4 + 0] = t.x; v[q * 4 + 1] = t.y;
        v[q * 4 + 2] = t.z; v[q * 4 + 3] = t.w;
        *(float4*)&orow[base] = z4;
    }
    // col(t) = 4*tid + 1024*(t>>2) + (t&3)

    float lv = v[0];
    int li = 4 * tid;
    #pragma unroll
    for (int t = 1; t < 32; t++) {
        const int ct = 4 * tid + 1024 * (t >> 2) + (t & 3);
        if (v[t] > lv || (v[t] == lv && ct < li)) { lv = v[t]; li = ct; }
    }

    __shared__ float swv[8];
    __shared__ int   swi[8];
    __shared__ int   sbi;
    __shared__ float topv[TOPK];
    __shared__ int   topi[TOPK];

    for (int it = 0; it < TOPK; it++) {
        float rv = lv; int ri = li;
        #pragma unroll
        for (int off = 16; off; off >>= 1) {
            float ov = __shfl_down_sync(0xffffffffu, rv, off);
            int   oi = __shfl_down_sync(0xffffffffu, ri, off);
            if (ov > rv || (ov == rv && oi < ri)) { rv = ov; ri = oi; }
        }
        if ((tid & 31) == 0) { swv[tid >> 5] = rv; swi[tid >> 5] = ri; }
        __syncthreads();
        if (tid == 0) {
            float bv = swv[0]; int bidx = swi[0];
            #pragma unroll
            for (int w = 1; w < 8; w++)
                if (swv[w] > bv || (swv[w] == bv && swi[w] < bidx)) { bv = swv[w]; bidx = swi[w]; }
            sbi = bidx; topv[it] = bv; topi[it] = bidx;
        }
        __syncthreads();
        const int bidx = sbi;
        if (li == bidx) {  // unique owner removes and rescans
            lv = -FLT_MAX; li = 0x7fffffff;
            #pragma unroll
            for (int t = 0; t < 32; t++) {
                const int ct = 4 * tid + 1024 * (t >> 2) + (t & 3);
                if (ct == bidx) v[t] = -FLT_MAX;
                if (v[t] > lv || (v[t] == lv && ct < li)) { lv = v[t]; li = ct; }
            }
        }
        __syncthreads();
    }

    if (tid < TOPK) {
        const float val = topv[tid];
        const int dst = topi[tid];
        orow[dst] = val;
        if (write_edges) {
            const long long e = (long long)row * TOPK + tid;
            out[e] = (float)row;                                // src
            out[(long long)NN * TOPK + e] = (float)dst;         // dst
            out[2LL * NN * TOPK + e] = val;                     // attr
        }
    }
}

// ============================================================================
// launch
// ============================================================================
extern "C" void kernel_launch(void* const* d_in, const int* in_sizes, int n_in,
                              void* d_out, int out_size)
{
    const float* E1 = (const float*)d_in[0];
    const float* E2 = (const float*)d_in[1];
    const float* W1 = (const float*)d_in[2];
    const float* b1 = (const float*)d_in[3];
    const float* W2 = (const float*)d_in[4];
    const float* b2 = (const float*)d_in[5];
    float* out = (float*)d_out;

    cudaFuncSetAttribute(prep_kernel, cudaFuncAttributeMaxDynamicSharedMemorySize, 81920);
    cudaFuncSetAttribute(gemm_kernel, cudaFuncAttributeMaxDynamicSharedMemorySize, 65536);

    long long abase;
    int write_edges;
    if (out_size == (long long)NN * NN) { abase = 0; write_edges = 0; }
    else { abase = 3LL * NN * TOPK; write_edges = 1; }

    prep_kernel<<<NN / 32, 256, 81920>>>(E1, W1, b1, 0);
    prep_kernel<<<NN / 32, 256, 81920>>>(E2, W2, b2, 1);
    gemm_kernel<<<dim3(64, 64), 256, 65536>>>();
    topk_kernel<<<NN, 256>>>(out, abase, write_edges);
}

// round 4
// speedup vs baseline: 1.5302x; 1.5302x over previous
#include <cuda_runtime.h>
#include <math.h>
#include <float.h>
#include <stdint.h>

#define NN 8192
#define DD 128
#define TOPK 30

typedef unsigned long long u64;

// ---- scratch (device globals; no runtime allocation allowed) ----
__device__ float g_M1t[DD * NN];              // M1^T  [128][8192]
__device__ float g_M2t[DD * NN];              // M2^T  [128][8192]
__device__ float g_A[(size_t)NN * NN];        // A scratch, 256 MB

// ============================================================================
// packed f32x2 helpers (Blackwell sm_103a): 2 IEEE fp32 FMAs per issue slot,
// bit-exact per lane.
// ============================================================================
__device__ __forceinline__ void fma2(u64& d, u64 a, u64 b) {
    asm("fma.rn.f32x2 %0, %1, %2, %0;" : "+l"(d) : "l"(a), "l"(b));
}
__device__ __forceinline__ u64 pack2(float x) {
    u64 r; asm("mov.b64 %0, {%1, %1};" : "=l"(r) : "f"(x)); return r;
}
__device__ __forceinline__ float2 unpk(u64 x) {
    float2 f; asm("mov.b64 {%0, %1}, %2;" : "=f"(f.x), "=f"(f.y) : "l"(x)); return f;
}

// ============================================================================
// XLA/Eigen f32 tanh replica (EmitTanh / generic_fast_tanh_float).
// ============================================================================
__device__ __forceinline__ float xla_tanh(float x) {
    const float kClamp = 7.90531110763549805f;
    const bool tiny = fabsf(x) < 0.0004f;
    float xc = fminf(fmaxf(x, -kClamp), kClamp);
    float x2 = xc * xc;
    float p = fmaf(x2, -2.76076847742355e-16f, 2.00018790482477e-13f);
    p = fmaf(x2, p, -8.60467152213735e-11f);
    p = fmaf(x2, p, 5.12229709037114e-08f);
    p = fmaf(x2, p, 1.48572235717979e-05f);
    p = fmaf(x2, p, 6.37261928875436e-04f);
    p = fmaf(x2, p, 4.89352455891786e-03f);
    p = xc * p;
    float q = fmaf(x2, 1.19825839466702e-06f, 1.18534705686654e-04f);
    q = fmaf(x2, q, 2.26843463243900e-03f);
    q = fmaf(x2, q, 4.89352518554385e-03f);
    float r = __fdiv_rn(p, q);
    return tiny ? x : r;
}

// ============================================================================
// Kernel 1: M = tanh(3*(E @ W^T + b)); transposed store, mode selects target.
// ============================================================================
__global__ void prep_kernel(const float* __restrict__ E,
                            const float* __restrict__ W,
                            const float* __restrict__ b,
                            int mode)
{
    extern __shared__ float sh[];
    float* Ws = sh;               // 128*128
    float* Es = sh + DD * DD;     // 32*128
    __shared__ float bs[DD];

    float* __restrict__ Mt = (mode == 0) ? g_M1t : g_M2t;

    const int tid = threadIdx.x;
    const int row0 = blockIdx.x * 32;

    {
        const float4* W4 = (const float4*)W;
        float4* Ws4 = (float4*)Ws;
        #pragma unroll 4
        for (int i = tid; i < DD * DD / 4; i += 256) Ws4[i] = W4[i];
        const float4* E4 = (const float4*)(E + (size_t)row0 * DD);
        float4* Es4 = (float4*)Es;
        #pragma unroll
        for (int i = tid; i < 32 * DD / 4; i += 256) Es4[i] = E4[i];
        if (tid < DD) bs[tid] = b[tid];
    }
    __syncthreads();

    const int tx = tid & 7;
    const int ty = tid >> 3;

    float acc[4][4];
    #pragma unroll
    for (int r = 0; r < 4; r++)
        #pragma unroll
        for (int c = 0; c < 4; c++) acc[r][c] = 0.0f;

    #pragma unroll 8
    for (int k = 0; k < DD; k += 4) {
        float4 ev[4], wv[4];
        #pragma unroll
        for (int r = 0; r < 4; r++) ev[r] = *(const float4*)&Es[(tx * 4 + r) * DD + k];
        #pragma unroll
        for (int c = 0; c < 4; c++) wv[c] = *(const float4*)&Ws[(ty * 4 + c) * DD + k];
        #pragma unroll
        for (int r = 0; r < 4; r++)
            #pragma unroll
            for (int c = 0; c < 4; c++) {
                acc[r][c] = fmaf(ev[r].x, wv[c].x, acc[r][c]);
                acc[r][c] = fmaf(ev[r].y, wv[c].y, acc[r][c]);
                acc[r][c] = fmaf(ev[r].z, wv[c].z, acc[r][c]);
                acc[r][c] = fmaf(ev[r].w, wv[c].w, acc[r][c]);
            }
    }

    #pragma unroll
    for (int r = 0; r < 4; r++) {
        const int row = row0 + tx * 4 + r;
        #pragma unroll
        for (int c = 0; c < 4; c++) {
            const int d = ty * 4 + c;
            const float t = acc[r][c] + bs[d];
            const float u = 3.0f * t;
            Mt[(size_t)d * NN + row] = xla_tanh(u);
        }
    }
}

// ============================================================================
// Kernel 2: P = M1@M2^T, Q = M2@M1^T via packed f32x2 FMA chains (ascending k,
// bit-exact per element). Upper-tri tiles only; A[j,i] = relu(Q-P) bitwise.
// ============================================================================
#define BK 16
#define NCHUNK (DD / BK)

__device__ __forceinline__ void cp16(uint32_t smem_dst, const float* gsrc) {
    asm volatile("cp.async.ca.shared.global [%0], [%1], 16;\n"
                 :: "r"(smem_dst), "l"(gsrc));
}

__global__ void __launch_bounds__(256) gemm_kernel()
{
    const int bi = blockIdx.y;
    const int bj = blockIdx.x;
    if (bj < bi) return;

    extern __shared__ float sh[];
    const int ARR = BK * 128;
    const int BUF = 4 * ARR;

    const int I0 = bi * 128, J0 = bj * 128;
    const int tid = threadIdx.x;
    const int tx = tid & 15;
    const int ty = tid >> 4;

    const uint32_t sbase = (uint32_t)__cvta_generic_to_shared(sh);

    int la[8], lk[8], lq[8];
    #pragma unroll
    for (int j = 0; j < 8; j++) {
        const int f = tid + 256 * j;
        la[j] = f >> 9;
        lk[j] = (f & 511) >> 5;
        lq[j] = f & 31;
    }

    auto issue_chunk = [&](int c, int buf) {
        const int kb = c * BK;
        #pragma unroll
        for (int j = 0; j < 8; j++) {
            const size_t gk = (size_t)(kb + lk[j]) * NN;
            const int col = ((la[j] & 1) ? J0 : I0) + lq[j] * 4;
            const float* src = ((la[j] & 2) ? g_M2t : g_M1t) + gk + col;
            cp16(sbase + (uint32_t)((buf * BUF + la[j] * ARR + lk[j] * 128 + lq[j] * 4) * 4), src);
        }
        asm volatile("cp.async.commit_group;\n");
    };

    issue_chunk(0, 0);

    u64 accP2[8][4], accQ2[8][4];
    #pragma unroll
    for (int r = 0; r < 8; r++)
        #pragma unroll
        for (int p = 0; p < 4; p++) { accP2[r][p] = 0ULL; accQ2[r][p] = 0ULL; }

    for (int c = 0; c < NCHUNK; c++) {
        const int cur = c & 1;
        if (c < NCHUNK - 1) {
            issue_chunk(c + 1, cur ^ 1);
            asm volatile("cp.async.wait_group 1;\n");
        } else {
            asm volatile("cp.async.wait_group 0;\n");
        }
        __syncthreads();

        const float* M1I = sh + cur * BUF + 0 * ARR;
        const float* M1J = sh + cur * BUF + 1 * ARR;
        const float* M2I = sh + cur * BUF + 2 * ARR;
        const float* M2J = sh + cur * BUF + 3 * ARR;

        #pragma unroll
        for (int kk = 0; kk < BK; kk++) {
            u64 a1d[8], a2d[8], b1p[4], b2p[4];
            {
                float4 t0 = *(const float4*)&M1I[kk * 128 + ty * 8];
                float4 t1 = *(const float4*)&M1I[kk * 128 + ty * 8 + 4];
                a1d[0]=pack2(t0.x); a1d[1]=pack2(t0.y); a1d[2]=pack2(t0.z); a1d[3]=pack2(t0.w);
                a1d[4]=pack2(t1.x); a1d[5]=pack2(t1.y); a1d[6]=pack2(t1.z); a1d[7]=pack2(t1.w);
                float4 u0 = *(const float4*)&M2I[kk * 128 + ty * 8];
                float4 u1 = *(const float4*)&M2I[kk * 128 + ty * 8 + 4];
                a2d[0]=pack2(u0.x); a2d[1]=pack2(u0.y); a2d[2]=pack2(u0.z); a2d[3]=pack2(u0.w);
                a2d[4]=pack2(u1.x); a2d[5]=pack2(u1.y); a2d[6]=pack2(u1.z); a2d[7]=pack2(u1.w);
                ulonglong2 q0 = *(const ulonglong2*)&M1J[kk * 128 + tx * 8];
                ulonglong2 q1 = *(const ulonglong2*)&M1J[kk * 128 + tx * 8 + 4];
                b1p[0]=q0.x; b1p[1]=q0.y; b1p[2]=q1.x; b1p[3]=q1.y;
                ulonglong2 w0 = *(const ulonglong2*)&M2J[kk * 128 + tx * 8];
                ulonglong2 w1 = *(const ulonglong2*)&M2J[kk * 128 + tx * 8 + 4];
                b2p[0]=w0.x; b2p[1]=w0.y; b2p[2]=w1.x; b2p[3]=w1.y;
            }
            #pragma unroll
            for (int r = 0; r < 8; r++)
                #pragma unroll
                for (int p = 0; p < 4; p++) {
                    fma2(accP2[r][p], a1d[r], b2p[p]);  // M1_i . M2_j
                    fma2(accQ2[r][p], a2d[r], b1p[p]);  // M2_i . M1_j
                }
        }
        __syncthreads();
    }

    // unpack to scalar accumulators
    float accP[8][8], accQ[8][8];
    #pragma unroll
    for (int r = 0; r < 8; r++)
        #pragma unroll
        for (int p = 0; p < 4; p++) {
            float2 fp = unpk(accP2[r][p]);
            float2 fq = unpk(accQ2[r][p]);
            accP[r][2*p] = fp.x; accP[r][2*p+1] = fp.y;
            accQ[r][2*p] = fq.x; accQ[r][2*p+1] = fq.y;
        }

    const int ibase = I0 + ty * 8;
    const int jbase = J0 + tx * 8;

    if (bi == bj) {
        #pragma unroll
        for (int r = 0; r < 8; r++) {
            const int ig = ibase + r;
            #pragma unroll
            for (int sg = 0; sg < 2; sg++) {
                float4 w;
                float* wp = &w.x;
                #pragma unroll
                for (int cc = 0; cc < 4; cc++) {
                    const int jg = jbase + sg * 4 + cc;
                    float x = fmaxf(accP[r][sg * 4 + cc] - accQ[r][sg * 4 + cc], 0.0f);
                    if (ig == jg) x = 0.0f;
                    wp[cc] = x;
                }
                *(float4*)&g_A[(size_t)ig * NN + jbase + sg * 4] = w;
            }
        }
    } else {
        #pragma unroll
        for (int r = 0; r < 8; r++) {
            #pragma unroll
            for (int sg = 0; sg < 2; sg++) {
                float4 w;
                float* wp = &w.x;
                #pragma unroll
                for (int cc = 0; cc < 4; cc++)
                    wp[cc] = fmaxf(accP[r][sg * 4 + cc] - accQ[r][sg * 4 + cc], 0.0f);
                *(float4*)&g_A[(size_t)(ibase + r) * NN + jbase + sg * 4] = w;
            }
        }
        #pragma unroll
        for (int s = 0; s < 8; s++) {
            const int jg = jbase + s;
            #pragma unroll
            for (int rg = 0; rg < 2; rg++) {
                float4 w;
                float* wp = &w.x;
                #pragma unroll
                for (int cc = 0; cc < 4; cc++)
                    wp[cc] = fmaxf(accQ[rg * 4 + cc][s] - accP[rg * 4 + cc][s], 0.0f);
                *(float4*)&g_A[(size_t)jg * NN + ibase + rg * 4] = w;
            }
        }
    }
}

// ============================================================================
// Kernel 3: per-row top-30 via per-thread bitonic sort + per-warp sorted-list
// merge + final 8-way merge. Keys: (valbits<<13)|(8191-col): descending key
// == descending val, ties lower col first (positive floats uint-monotone).
// dyn smem = 65536 B (per-thread sorted lists).
// ============================================================================
__device__ __forceinline__ u64 shfl64_xor(u64 x, int off) {
    unsigned lo = (unsigned)x, hi = (unsigned)(x >> 32);
    lo = __shfl_xor_sync(0xffffffffu, lo, off);
    hi = __shfl_xor_sync(0xffffffffu, hi, off);
    return ((u64)hi << 32) | lo;
}

__global__ void __launch_bounds__(256) topk_kernel(float* __restrict__ out,
                                                   long long abase,
                                                   int write_edges)
{
    extern __shared__ u64 lists[];            // [256][32]
    __shared__ u64 wtop[8][TOPK];
    __shared__ u64 topkeys[TOPK];

    const int row = blockIdx.x;
    const int tid = threadIdx.x;
    const int lane = tid & 31;
    const int w = tid >> 5;
    const float* arow = g_A + (size_t)row * NN;
    float* orow = out + abase + (size_t)row * NN;

    // load 32 values, zero output row, pack keys
    u64 k[32];
    const float4 z4 = make_float4(0.f, 0.f, 0.f, 0.f);
    #pragma unroll
    for (int q = 0; q < 8; q++) {
        const int base = (tid + 256 * q) * 4;
        float4 t = *(const float4*)&arow[base];
        *(float4*)&orow[base] = z4;
        // col = base + c
        k[q*4+0] = ((u64)__float_as_uint(t.x) << 13) | (u64)(8191 - (base + 0));
        k[q*4+1] = ((u64)__float_as_uint(t.y) << 13) | (u64)(8191 - (base + 1));
        k[q*4+2] = ((u64)__float_as_uint(t.z) << 13) | (u64)(8191 - (base + 2));
        k[q*4+3] = ((u64)__float_as_uint(t.w) << 13) | (u64)(8191 - (base + 3));
    }

    // per-thread bitonic sort, descending
    #pragma unroll
    for (int size = 2; size <= 32; size <<= 1) {
        #pragma unroll
        for (int stride = size >> 1; stride > 0; stride >>= 1) {
            #pragma unroll
            for (int i = 0; i < 32; i++) {
                const int j = i ^ stride;
                if (j > i) {
                    const bool desc = ((i & size) == 0);
                    const u64 lo = (k[i] < k[j]) ? k[i] : k[j];
                    const u64 hi = (k[i] < k[j]) ? k[j] : k[i];
                    k[i] = desc ? hi : lo;
                    k[j] = desc ? lo : hi;
                }
            }
        }
    }

    // dump sorted list to smem (dynamic head indexing during merge)
    u64* mylist = lists + tid * 32;
    #pragma unroll
    for (int i = 0; i < 32; i++) mylist[i] = k[i];

    // per-warp merge: 30 pops over 32 sorted lists (keys unique -> owner test)
    {
        int h = 0;
        u64 head = k[0];
        for (int it = 0; it < TOPK; it++) {
            u64 m = head;
            #pragma unroll
            for (int off = 16; off; off >>= 1) {
                u64 om = shfl64_xor(m, off);
                if (om > m) m = om;
            }
            if (lane == 0) wtop[w][it] = m;
            if (head == m) { h++; head = mylist[h]; }  // h <= 30 < 32, in range
        }
    }
    __syncthreads();

    // final merge: warp 0, lanes 0..7 hold list heads
    if (w == 0) {
        int h = 0;
        u64 head = (lane < 8) ? wtop[lane][0] : 0ULL;
        for (int it = 0; it < TOPK; it++) {
            u64 m = head;
            #pragma unroll
            for (int off = 4; off; off >>= 1) {
                u64 om = shfl64_xor(m, off);
                if (om > m) m = om;
            }
            if (lane == 0) topkeys[it] = m;
            if (lane < 8 && head == m) {
                h++;
                head = (h < TOPK) ? wtop[lane][h] : 0ULL;
            }
        }
    }
    __syncthreads();

    if (tid < TOPK) {
        const u64 key = topkeys[tid];
        const float val = __uint_as_float((unsigned)(key >> 13));
        const int dst = 8191 - (int)(key & 8191);
        orow[dst] = val;
        if (write_edges) {
            const long long e = (long long)row * TOPK + tid;
            out[e] = (float)row;                                // src
            out[(long long)NN * TOPK + e] = (float)dst;         // dst
            out[2LL * NN * TOPK + e] = val;                     // attr
        }
    }
}

// ============================================================================
// launch
// ============================================================================
extern "C" void kernel_launch(void* const* d_in, const int* in_sizes, int n_in,
                              void* d_out, int out_size)
{
    const float* E1 = (const float*)d_in[0];
    const float* E2 = (const float*)d_in[1];
    const float* W1 = (const float*)d_in[2];
    const float* b1 = (const float*)d_in[3];
    const float* W2 = (const float*)d_in[4];
    const float* b2 = (const float*)d_in[5];
    float* out = (float*)d_out;

    cudaFuncSetAttribute(prep_kernel, cudaFuncAttributeMaxDynamicSharedMemorySize, 81920);
    cudaFuncSetAttribute(gemm_kernel, cudaFuncAttributeMaxDynamicSharedMemorySize, 65536);
    cudaFuncSetAttribute(topk_kernel, cudaFuncAttributeMaxDynamicSharedMemorySize, 65536);

    long long abase;
    int write_edges;
    if (out_size == (long long)NN * NN) { abase = 0; write_edges = 0; }
    else { abase = 3LL * NN * TOPK; write_edges = 1; }

    prep_kernel<<<NN / 32, 256, 81920>>>(E1, W1, b1, 0);
    prep_kernel<<<NN / 32, 256, 81920>>>(E2, W2, b2, 1);
    gemm_kernel<<<dim3(64, 64), 256, 65536>>>();
    topk_kernel<<<NN, 256, 65536>>>(out, abase, write_edges);
}